// round 3
// baseline (speedup 1.0000x reference)
#include <cuda_runtime.h>
#include <cstdint>

#define M_TOTAL 16384
#define N_TOTAL 1024
#define K_TOTAL 1024
#define L_CONV  20

// Scratch: reduced + tf32-rounded weight (device globals are the sanctioned scratch)
__device__ float g_W[(size_t)N_TOTAL * K_TOTAL];   // 4MB

// ---------------------------------------------------------------------------
// Baseline-PTX helpers (sm_80-era features only — no tcgen05 on this target)
// ---------------------------------------------------------------------------
__device__ __forceinline__ uint32_t smem_u32(const void* p) {
    uint32_t a;
    asm("{ .reg .u64 t; cvta.to.shared.u64 t, %1; cvt.u32.u64 %0, t; }"
        : "=r"(a) : "l"(p));
    return a;
}

__device__ __forceinline__ uint32_t f2tf32(float x) {
    uint32_t r;
    asm("cvt.rna.tf32.f32 %0, %1;" : "=r"(r) : "f"(x));
    return r;
}

__device__ __forceinline__ float tf32_rna_f(float x) {
    float r;
    asm("cvt.rna.tf32.f32 %0, %1;" : "=f"(r) : "f"(x));
    return r;
}

#define CP_ASYNC16(dst, src) \
    asm volatile("cp.async.cg.shared.global [%0], [%1], 16;" \
                 :: "r"(dst), "l"(src))
#define CP_COMMIT() asm volatile("cp.async.commit_group;")
#define CP_WAIT(n)  asm volatile("cp.async.wait_group %0;" :: "n"(n))

#define LDSM4(R, addr) \
    asm volatile("ldmatrix.sync.aligned.m8n8.x4.shared.b16 {%0,%1,%2,%3}, [%4];" \
                 : "=r"((R)[0]), "=r"((R)[1]), "=r"((R)[2]), "=r"((R)[3]) \
                 : "r"(addr))

#define MMA_TF32(D, A, B0, B1) \
    asm volatile("mma.sync.aligned.m16n8k8.row.col.f32.tf32.tf32.f32 " \
                 "{%0,%1,%2,%3}, {%4,%5,%6,%7}, {%8,%9}, {%0,%1,%2,%3};" \
                 : "+f"((D)[0]), "+f"((D)[1]), "+f"((D)[2]), "+f"((D)[3]) \
                 : "r"((A)[0]), "r"((A)[1]), "r"((A)[2]), "r"((A)[3]), \
                   "r"(B0), "r"(B1))

// ---------------------------------------------------------------------------
// Kernel 1: W[o,i] = round_tf32( (1/L) * sum_l conv_w[l,o,i] )
// ---------------------------------------------------------------------------
__global__ void reduce_w_kernel(const float* __restrict__ cw) {
    size_t i = (size_t)blockIdx.x * blockDim.x + threadIdx.x;  // over 262144 float4
    const float4* c4 = (const float4*)cw;
    const size_t plane = (size_t)N_TOTAL * K_TOTAL / 4;
    float4 a = c4[i];
    #pragma unroll
    for (int l = 1; l < L_CONV; ++l) {
        float4 v = c4[(size_t)l * plane + i];
        a.x += v.x; a.y += v.y; a.z += v.z; a.w += v.w;
    }
    const float s = 1.0f / (float)L_CONV;
    a.x = tf32_rna_f(a.x * s); a.y = tf32_rna_f(a.y * s);
    a.z = tf32_rna_f(a.z * s); a.w = tf32_rna_f(a.w * s);
    ((float4*)g_W)[i] = a;
}

// ---------------------------------------------------------------------------
// Kernel 2: tf32 GEMM via mma.sync — CTA tile 128x128, BK=32, 3-stage cp.async
//   A = x [16384 x 1024] row-major (K-major)
//   B = g_W [1024 x 1024] row-major in (n,k) == col-major B for .row.col mma
// ---------------------------------------------------------------------------
#define BM 128
#define BN 128
#define BK 32
#define ROWSTRIDE_B 144                    // 36 floats: padded, conflict-free
#define TILE_BYTES (128 * ROWSTRIDE_B)     // 18432
#define STAGE_BYTES (2 * TILE_BYTES)       // 36864 (A then B)
#define NSTAGES 3
#define GEMM_SMEM (NSTAGES * STAGE_BYTES)  // 110592
#define KTILES (K_TOTAL / BK)              // 32

__global__ __launch_bounds__(256, 2) void gemm_kernel(const float* __restrict__ x,
                                                      float* __restrict__ out) {
    extern __shared__ __align__(128) char smem[];
    const uint32_t sbase = smem_u32(smem);
    const int tid  = threadIdx.x;
    const int lane = tid & 31;
    const int warp = tid >> 5;
    const int wm = warp & 3;          // 4 warps along M (32 rows each)
    const int wn = warp >> 2;         // 2 warps along N (64 cols each)
    const int m0 = blockIdx.y * BM;
    const int n0 = blockIdx.x * BN;

    // --- global->smem copy assignments: 4 A chunks + 4 B chunks (16B) per thread
    const float* asrc[4];
    const float* bsrc[4];
    uint32_t adst[4], bdst[4];
    #pragma unroll
    for (int j = 0; j < 4; ++j) {
        int id  = tid + j * 256;          // 0..1023
        int row = id >> 3;                // 0..127
        int u   = id & 7;                 // 16B chunk within 128B row
        asrc[j] = x + (size_t)(m0 + row) * K_TOTAL + u * 4;
        bsrc[j] = g_W + (size_t)(n0 + row) * K_TOTAL + u * 4;
        adst[j] = sbase + row * ROWSTRIDE_B + u * 16;
        bdst[j] = sbase + TILE_BYTES + row * ROWSTRIDE_B + u * 16;
    }

    // --- ldmatrix per-thread addresses (stage/k offsets added later)
    const int r8 = lane & 7;
    const int g  = lane >> 3;
    uint32_t a_addr[2], b_addr[4];
    #pragma unroll
    for (int mt = 0; mt < 2; ++mt) {
        // regs: r0=a0(rows+0,b0..15) r1=a1(rows+8,b0..15) r2=a2(rows+0,b16..31) r3=a3(rows+8,+16)
        int arow = wm * 32 + mt * 16 + ((g & 1) << 3) + r8;
        a_addr[mt] = sbase + arow * ROWSTRIDE_B + ((g >> 1) << 4);
    }
    #pragma unroll
    for (int p = 0; p < 4; ++p) {
        // regs: r0=b0(ntile 2p) r1=b1(ntile 2p) r2=b0(ntile 2p+1) r3=b1(ntile 2p+1)
        int brow = wn * 64 + p * 16 + ((g >> 1) << 3) + r8;
        b_addr[p] = sbase + TILE_BYTES + brow * ROWSTRIDE_B + ((g & 1) << 4);
    }

    float c[2][8][4];
    #pragma unroll
    for (int mt = 0; mt < 2; ++mt)
        #pragma unroll
        for (int nt = 0; nt < 8; ++nt)
            #pragma unroll
            for (int i = 0; i < 4; ++i) c[mt][nt][i] = 0.0f;

    // --- prologue: prefetch first NSTAGES-1 k-tiles
    #pragma unroll
    for (int s = 0; s < NSTAGES - 1; ++s) {
        uint32_t soff = s * STAGE_BYTES;
        #pragma unroll
        for (int j = 0; j < 4; ++j) {
            CP_ASYNC16(adst[j] + soff, asrc[j] + s * BK);
            CP_ASYNC16(bdst[j] + soff, bsrc[j] + s * BK);
        }
        CP_COMMIT();
    }

    // --- main loop
    for (int kt = 0; kt < KTILES; ++kt) {
        CP_WAIT(NSTAGES - 2);
        __syncthreads();

        int nload = kt + NSTAGES - 1;
        if (nload < KTILES) {
            uint32_t soff = (nload % NSTAGES) * STAGE_BYTES;
            #pragma unroll
            for (int j = 0; j < 4; ++j) {
                CP_ASYNC16(adst[j] + soff, asrc[j] + nload * BK);
                CP_ASYNC16(bdst[j] + soff, bsrc[j] + nload * BK);
            }
        }
        CP_COMMIT();

        const uint32_t soff = (kt % NSTAGES) * STAGE_BYTES;
        #pragma unroll
        for (int kk = 0; kk < 4; ++kk) {          // 4 x k8 steps
            uint32_t a[2][4], b[4][4];
            LDSM4(a[0], a_addr[0] + soff + kk * 32);
            LDSM4(a[1], a_addr[1] + soff + kk * 32);
            #pragma unroll
            for (int p = 0; p < 4; ++p)
                LDSM4(b[p], b_addr[p] + soff + kk * 32);
            // round A to tf32 (rna) — B was pre-rounded in reduce_w
            #pragma unroll
            for (int mt = 0; mt < 2; ++mt)
                #pragma unroll
                for (int i = 0; i < 4; ++i)
                    a[mt][i] = f2tf32(__uint_as_float(a[mt][i]));
            #pragma unroll
            for (int mt = 0; mt < 2; ++mt)
                #pragma unroll
                for (int nt = 0; nt < 8; ++nt) {
                    const int p = nt >> 1, h = (nt & 1) * 2;
                    MMA_TF32(c[mt][nt], a[mt], b[p][h], b[p][h + 1]);
                }
        }
    }

    // --- epilogue: direct float2 stores of raw y
    #pragma unroll
    for (int mt = 0; mt < 2; ++mt) {
        #pragma unroll
        for (int nt = 0; nt < 8; ++nt) {
            int row = m0 + wm * 32 + mt * 16 + (lane >> 2);
            int col = n0 + wn * 64 + nt * 8 + ((lane & 3) * 2);
            *(float2*)(out + (size_t)row * N_TOTAL + col) =
                make_float2(c[mt][nt][0], c[mt][nt][1]);
            *(float2*)(out + (size_t)(row + 8) * N_TOTAL + col) =
                make_float2(c[mt][nt][2], c[mt][nt][3]);
        }
    }
}

// ---------------------------------------------------------------------------
// Kernel 3: in-place RMSNorm over H=1024 per row
// ---------------------------------------------------------------------------
__global__ void rmsnorm_kernel(float* __restrict__ out, const float* __restrict__ nw) {
    const int row = blockIdx.x;
    const int tid = threadIdx.x;   // 256 threads, 1 float4 each
    float4* p = (float4*)(out + (size_t)row * 1024);
    float4 v = p[tid];
    float ss = v.x * v.x + v.y * v.y + v.z * v.z + v.w * v.w;
    #pragma unroll
    for (int o = 16; o > 0; o >>= 1) ss += __shfl_xor_sync(0xffffffffu, ss, o);
    __shared__ float sred[8];
    if ((tid & 31) == 0) sred[tid >> 5] = ss;
    __syncthreads();
    float tot = sred[0] + sred[1] + sred[2] + sred[3] +
                sred[4] + sred[5] + sred[6] + sred[7];
    float sc = rsqrtf(tot * (1.0f / 1024.0f) + 1e-6f);
    float4 w = ((const float4*)nw)[tid];
    v.x *= sc * w.x; v.y *= sc * w.y; v.z *= sc * w.z; v.w *= sc * w.w;
    p[tid] = v;
}

// ---------------------------------------------------------------------------
extern "C" void kernel_launch(void* const* d_in, const int* in_sizes, int n_in,
                              void* d_out, int out_size) {
    const float* xin = (const float*)d_in[0];
    const float* cw  = (const float*)d_in[1];
    const float* nw  = (const float*)d_in[2];
    float* out = (float*)d_out;

    reduce_w_kernel<<<512, 512>>>(cw);              // 262144 float4

    cudaFuncSetAttribute(gemm_kernel, cudaFuncAttributeMaxDynamicSharedMemorySize,
                         GEMM_SMEM);
    gemm_kernel<<<dim3(N_TOTAL / BN, M_TOTAL / BM), 256, GEMM_SMEM>>>(xin, out);

    rmsnorm_kernel<<<M_TOTAL, 256>>>(out, nw);
}